// round 4
// baseline (speedup 1.0000x reference)
#include <cuda_runtime.h>

#define BB 256
#define TT 512
#define DD 50
#define HH 128
#define G4 512
#define HID 256

typedef unsigned long long ull;

// ---- device scratch ----
__device__ float g_xgT[2][TT][G4][BB];   // input-gate preactivations, transposed [d][t][row][b]

__device__ __forceinline__ float sigf(float x)   { return 1.0f / (1.0f + __expf(-x)); }
__device__ __forceinline__ float tanhf_(float x) { return 2.0f / (1.0f + __expf(-2.0f * x)) - 1.0f; }

__device__ __forceinline__ ull pack2(float a, float b) {
    ull r; asm("mov.b64 %0,{%1,%2};" : "=l"(r) : "f"(a), "f"(b)); return r;
}
__device__ __forceinline__ void unpack2(ull v, float& a, float& b) {
    asm("mov.b64 {%0,%1},%2;" : "=f"(a), "=f"(b) : "l"(v));
}
__device__ __forceinline__ void fma2(ull a, ull b, ull& c) {
    asm("fma.rn.f32x2 %0,%1,%2,%0;" : "+l"(c) : "l"(a), "l"(b));
}
__device__ __forceinline__ unsigned smem_u32(const void* p) {
    unsigned r;
    asm("{ .reg .u64 t; cvta.to.shared.u64 t, %1; cvt.u32.u64 %0, t; }" : "=r"(r) : "l"(p));
    return r;
}

// ---------------------------------------------------------------------------
// Embedding lookup + input-gate GEMM -> transposed xg  (unchanged from R2)
// ---------------------------------------------------------------------------
__global__ void __launch_bounds__(256) embed_gemm(
    const int*   __restrict__ idx,
    const float* __restrict__ emb,
    const float* __restrict__ Wih_f, const float* __restrict__ bih_f, const float* __restrict__ bhh_f,
    const float* __restrict__ Wih_b, const float* __restrict__ bih_b, const float* __restrict__ bhh_b)
{
    __shared__ __align__(16) float xsA[16 * DD * 2];
    const int tid = threadIdx.x;
    const int b0  = blockIdx.x * 32;
    const int t   = blockIdx.y;

    for (int i = tid; i < 32 * DD; i += 256) {
        int b = i / DD, k = i - b * DD;
        int id = idx[(b0 + b) * TT + t];
        xsA[(b >> 1) * (2 * DD) + k * 2 + (b & 1)] = emb[id * DD + k];
    }
    __syncthreads();

    #pragma unroll 1
    for (int g = 0; g < 4; ++g) {
        int col = tid + g * 256;
        int dir = col >> 9;
        int n   = col & 511;
        const float* W = dir ? Wih_b : Wih_f;
        float bias = dir ? (bih_b[n] + bhh_b[n]) : (bih_f[n] + bhh_f[n]);

        float w[DD];
        #pragma unroll
        for (int k = 0; k < DD; ++k) w[k] = W[n * DD + k];

        ull acc[16];
        ull bp = pack2(bias, bias);
        #pragma unroll
        for (int p = 0; p < 16; ++p) acc[p] = bp;

        #pragma unroll 2
        for (int k = 0; k < DD; ++k) {
            ull w2 = pack2(w[k], w[k]);
            #pragma unroll
            for (int p = 0; p < 16; ++p) {
                ull x = *(const ull*)&xsA[p * (2 * DD) + k * 2];
                fma2(x, w2, acc[p]);
            }
        }

        float* dst = &g_xgT[dir][t][n][b0];
        #pragma unroll
        for (int p = 0; p < 16; ++p) {
            float a, b; unpack2(acc[p], a, b);
            *(float2*)&dst[2 * p] = make_float2(a, b);
        }
    }
}

// ---------------------------------------------------------------------------
// Persistent clustered LSTM recurrence.
// grid (8,8,2), cluster (8,1,1): 16 clusters, one per (dir, batch-tile).
// CTA = k-slice of 16; 256 threads; tile 32 batches x 64 gate rows.
// h exchanged by DSMEM push into peers' double-buffered smem tiles;
// per-step sync = split cluster barrier (no L1 flush, no global traffic).
// ---------------------------------------------------------------------------
// dyn smem layout (bytes):
//   [0,      32768)  wq   : weights, 8 warps x 128 k x 4 ull (row-pairs)
//   [32768,  49152)  hb0  : h tile [128 k][32 b]
//   [49152,  65536)  hb1  : h tile (double buffer)
//   [65536,  73728)  gbuf : gate exchange [64 rows][32 b]
#define SMEM_BYTES 73728

__global__ void __launch_bounds__(256, 1) __cluster_dims__(8, 1, 1)
lstm_cluster(const float* __restrict__ Whh_f, const float* __restrict__ Whh_b,
             const float* __restrict__ masks, float* __restrict__ out)
{
    extern __shared__ __align__(16) char smem[];
    ull*   wq   = (ull*)smem;
    float* hb[2];
    hb[0] = (float*)(smem + 32768);
    hb[1] = (float*)(smem + 49152);
    float* gbuf = (float*)(smem + 65536);

    const int tid  = threadIdx.x;
    const int ks   = blockIdx.x;          // k-slice == cluster rank
    const int bt   = blockIdx.y;
    const int d    = blockIdx.z;
    const int ks0  = ks * 16;
    const int bb0  = bt * 32;
    const int warp = tid >> 5;
    const int lane = tid & 31;

    const float* Whh = d ? Whh_b : Whh_f;

    // ---- stage weights once: wq[w][k][j] packs local rows (8w+2j, 8w+2j+1) ----
    for (int i = tid; i < 8192; i += 256) {
        int rl = i & 63, k = i >> 6;
        int g = rl >> 4, kk = rl & 15;
        float v = Whh[(g * 128 + ks0 + kk) * 128 + k];
        int w_ = rl >> 3, j = (rl & 7) >> 1, e = rl & 1;
        ((float*)wq)[((w_ * 128 + k) * 4 + j) * 2 + e] = v;
    }
    // zero h buffer for step 0
    for (int i = tid; i < 4096; i += 256) hb[0][i] = 0.f;

    // update-phase identity: k = uk, batches ub, ub+1
    const int uk = tid >> 4;               // 0..15
    const int ub = (tid & 15) * 2;         // 0,2,..,30
    float c0 = 0.f, c1 = 0.f;
    float m0 = -3.0e38f, m1 = -3.0e38f;

    // precomputed smem byte offsets of this thread's h destination in each buffer
    const unsigned hdst_off = (unsigned)(((ks0 + uk) * 32 + ub) * 4);
    const unsigned hb_u32[2] = { smem_u32(hb[0]) + hdst_off, smem_u32(hb[1]) + hdst_off };

    // prefetch xg for step 0
    const int tstep = d ? -1 : 1;
    int t = d ? (TT - 1) : 0;
    float xn[8];
    #pragma unroll
    for (int i = 0; i < 8; ++i) {
        int rl = 8 * warp + i;
        int g = rl >> 4, kk = rl & 15;
        xn[i] = __ldg(&g_xgT[d][t][g * 128 + ks0 + kk][bb0 + lane]);
    }
    float pen0 = (1.0f - __ldg(&masks[(bb0 + ub)     * TT + t])) * 1e8f;
    float pen1 = (1.0f - __ldg(&masks[(bb0 + ub + 1) * TT + t])) * 1e8f;

    // cluster-wide sync: weights staged, hb0 zeroed in every CTA
    asm volatile("barrier.cluster.arrive.aligned;" ::: "memory");
    asm volatile("barrier.cluster.wait.aligned;"   ::: "memory");

    int cur = 0;
    for (int s = 0; s < TT; ++s) {
        // ---- init accumulators from prefetched xg, then prefetch next step ----
        ull acc0 = pack2(xn[0], xn[1]);
        ull acc1 = pack2(xn[2], xn[3]);
        ull acc2 = pack2(xn[4], xn[5]);
        ull acc3 = pack2(xn[6], xn[7]);
        float npen0 = pen0, npen1 = pen1;

        {
            int t2 = t + tstep;
            t2 = (t2 < 0) ? 0 : (t2 > TT - 1 ? TT - 1 : t2);
            #pragma unroll
            for (int i = 0; i < 8; ++i) {
                int rl = 8 * warp + i;
                int g = rl >> 4, kk = rl & 15;
                xn[i] = __ldg(&g_xgT[d][t2][g * 128 + ks0 + kk][bb0 + lane]);
            }
            pen0 = (1.0f - __ldg(&masks[(bb0 + ub)     * TT + t2])) * 1e8f;
            pen1 = (1.0f - __ldg(&masks[(bb0 + ub + 1) * TT + t2])) * 1e8f;
        }

        // ---- gate preactivations: 8 rows x 32 batches per warp ----
        const float* hc = hb[cur];
        const ull*   wr = &wq[warp * 128 * 4];
        #pragma unroll 4
        for (int k = 0; k < 128; ++k) {
            float h = hc[k * 32 + lane];                        // conflict-free LDS.32
            ull h2 = pack2(h, h);
            ulonglong2 wa = *(const ulonglong2*)&wr[k * 4 + 0]; // uniform LDS.128
            ulonglong2 wb = *(const ulonglong2*)&wr[k * 4 + 2];
            fma2(h2, wa.x, acc0);
            fma2(h2, wa.y, acc1);
            fma2(h2, wb.x, acc2);
            fma2(h2, wb.y, acc3);
        }

        // ---- gate exchange (gbuf consumed last step before the barrier) ----
        {
            float a, b;
            unpack2(acc0, a, b); gbuf[(8 * warp + 0) * 32 + lane] = a; gbuf[(8 * warp + 1) * 32 + lane] = b;
            unpack2(acc1, a, b); gbuf[(8 * warp + 2) * 32 + lane] = a; gbuf[(8 * warp + 3) * 32 + lane] = b;
            unpack2(acc2, a, b); gbuf[(8 * warp + 4) * 32 + lane] = a; gbuf[(8 * warp + 5) * 32 + lane] = b;
            unpack2(acc3, a, b); gbuf[(8 * warp + 6) * 32 + lane] = a; gbuf[(8 * warp + 7) * 32 + lane] = b;
        }
        __syncthreads();

        // ---- c/h update + running masked max: thread -> (k=uk, batches ub,ub+1) ----
        float2 gi = *(const float2*)&gbuf[( 0 + uk) * 32 + ub];
        float2 gf = *(const float2*)&gbuf[(16 + uk) * 32 + ub];
        float2 gg = *(const float2*)&gbuf[(32 + uk) * 32 + ub];
        float2 go = *(const float2*)&gbuf[(48 + uk) * 32 + ub];

        c0 = sigf(gf.x) * c0 + sigf(gi.x) * tanhf_(gg.x);
        float hv0 = sigf(go.x) * tanhf_(c0);
        m0 = fmaxf(m0, hv0 - npen0);

        c1 = sigf(gf.y) * c1 + sigf(gi.y) * tanhf_(gg.y);
        float hv1 = sigf(go.y) * tanhf_(c1);
        m1 = fmaxf(m1, hv1 - npen1);

        if (s < TT - 1) {
            // push h slice into every cluster CTA's next h-buffer (incl. self)
            unsigned base = hb_u32[cur ^ 1];
            #pragma unroll
            for (int r = 0; r < 8; ++r) {
                unsigned ra;
                asm("mapa.shared::cluster.u32 %0, %1, %2;" : "=r"(ra) : "r"(base), "r"(r));
                asm volatile("st.shared::cluster.v2.f32 [%0], {%1,%2};"
                             :: "r"(ra), "f"(hv0), "f"(hv1) : "memory");
            }
            // release our stores / acquire everyone's; also orders gbuf reuse
            asm volatile("barrier.cluster.arrive.aligned;" ::: "memory");
            asm volatile("barrier.cluster.wait.aligned;"   ::: "memory");
        }

        cur ^= 1;
        t += tstep;
    }

    // final output: each thread owns (b=bb0+ub(+1), k=ks0+uk)
    out[(bb0 + ub)     * HID + d * HH + ks0 + uk] = m0;
    out[(bb0 + ub + 1) * HID + d * HH + ks0 + uk] = m1;
}

// ---------------------------------------------------------------------------
extern "C" void kernel_launch(void* const* d_in, const int* in_sizes, int n_in,
                              void* d_out, int out_size)
{
    (void)in_sizes; (void)n_in; (void)out_size;
    const int*   idx   = (const int*)  d_in[0];
    const float* masks = (const float*)d_in[1];
    const float* emb   = (const float*)d_in[2];
    const float* Wih_f = (const float*)d_in[3];
    const float* Whh_f = (const float*)d_in[4];
    const float* bih_f = (const float*)d_in[5];
    const float* bhh_f = (const float*)d_in[6];
    const float* Wih_b = (const float*)d_in[7];
    const float* Whh_b = (const float*)d_in[8];
    const float* bih_b = (const float*)d_in[9];
    const float* bhh_b = (const float*)d_in[10];
    float* out = (float*)d_out;

    static int configured = 0;
    if (!configured) {
        cudaFuncSetAttribute(lstm_cluster,
                             cudaFuncAttributeMaxDynamicSharedMemorySize, SMEM_BYTES);
        configured = 1;
    }

    embed_gemm<<<dim3(8, TT), 256>>>(idx, emb, Wih_f, bih_f, bhh_f,
                                     Wih_b, bih_b, bhh_b);
    lstm_cluster<<<dim3(8, 8, 2), 256, SMEM_BYTES>>>(Whh_f, Whh_b, masks, out);
}

// round 6
// speedup vs baseline: 1.6625x; 1.6625x over previous
#include <cuda_runtime.h>

#define BB 256
#define TT 512
#define DD 50
#define HH 128
#define G4 512
#define HID 256

typedef unsigned long long ull;

// ---- device scratch ----
__device__ float g_xgT[2][TT][G4][BB];   // input-gate preactivations [d][t][row][b]

__device__ __forceinline__ float sigf(float x)   { return 1.0f / (1.0f + __expf(-x)); }
__device__ __forceinline__ float tanhf_(float x) { return 2.0f / (1.0f + __expf(-2.0f * x)) - 1.0f; }

__device__ __forceinline__ ull pack2(float a, float b) {
    ull r; asm("mov.b64 %0,{%1,%2};" : "=l"(r) : "f"(a), "f"(b)); return r;
}
__device__ __forceinline__ void unpack2(ull v, float& a, float& b) {
    asm("mov.b64 {%0,%1},%2;" : "=f"(a), "=f"(b) : "l"(v));
}
__device__ __forceinline__ void fma2(ull a, ull b, ull& c) {
    asm("fma.rn.f32x2 %0,%1,%2,%0;" : "+l"(c) : "l"(a), "l"(b));
}
__device__ __forceinline__ unsigned smem_u32(const void* p) {
    unsigned r;
    asm("{ .reg .u64 t; cvta.to.shared.u64 t, %1; cvt.u32.u64 %0, t; }" : "=r"(r) : "l"(p));
    return r;
}

// ---------------------------------------------------------------------------
// Embedding lookup + input-gate GEMM -> transposed xg (unchanged)
// ---------------------------------------------------------------------------
__global__ void __launch_bounds__(256) embed_gemm(
    const int*   __restrict__ idx,
    const float* __restrict__ emb,
    const float* __restrict__ Wih_f, const float* __restrict__ bih_f, const float* __restrict__ bhh_f,
    const float* __restrict__ Wih_b, const float* __restrict__ bih_b, const float* __restrict__ bhh_b)
{
    __shared__ __align__(16) float xsA[16 * DD * 2];
    const int tid = threadIdx.x;
    const int b0  = blockIdx.x * 32;
    const int t   = blockIdx.y;

    for (int i = tid; i < 32 * DD; i += 256) {
        int b = i / DD, k = i - b * DD;
        int id = idx[(b0 + b) * TT + t];
        xsA[(b >> 1) * (2 * DD) + k * 2 + (b & 1)] = emb[id * DD + k];
    }
    __syncthreads();

    #pragma unroll 1
    for (int g = 0; g < 4; ++g) {
        int col = tid + g * 256;
        int dir = col >> 9;
        int n   = col & 511;
        const float* W = dir ? Wih_b : Wih_f;
        float bias = dir ? (bih_b[n] + bhh_b[n]) : (bih_f[n] + bhh_f[n]);

        float w[DD];
        #pragma unroll
        for (int k = 0; k < DD; ++k) w[k] = W[n * DD + k];

        ull acc[16];
        ull bp = pack2(bias, bias);
        #pragma unroll
        for (int p = 0; p < 16; ++p) acc[p] = bp;

        #pragma unroll 2
        for (int k = 0; k < DD; ++k) {
            ull w2 = pack2(w[k], w[k]);
            #pragma unroll
            for (int p = 0; p < 16; ++p) {
                ull x = *(const ull*)&xsA[p * (2 * DD) + k * 2];
                fma2(x, w2, acc[p]);
            }
        }

        float* dst = &g_xgT[dir][t][n][b0];
        #pragma unroll
        for (int p = 0; p < 16; ++p) {
            float a, b; unpack2(acc[p], a, b);
            *(float2*)&dst[2 * p] = make_float2(a, b);
        }
    }
}

// ---------------------------------------------------------------------------
// Persistent LSTM recurrence: 2-CTA clusters. (R4 design, stride bug fixed)
// grid (2 k-halves, 32 b-tiles of 8, 2 dirs) = 128 CTAs, cluster (2,1,1).
// CTA: 256 threads, owns 64 k-outputs x 8 batches, ALL 4 gates per thread.
// Weights (256 rows x 128 k = 128KB) live in smem for all 512 steps.
// Per-step exchange: 2KB DSMEM push to one peer + split cluster barrier.
// ---------------------------------------------------------------------------
// dyn smem: [0,131072) weights float (wi,wf,wg,wo) laid out [k 128][kk 64][g 4]
//           [131072,135168) hb0 [k 128][b 8]
//           [135168,139264) hb1
#define SMEM_BYTES 139264

__global__ void __launch_bounds__(256, 1) __cluster_dims__(2, 1, 1)
lstm_pair(const float* __restrict__ Whh_f, const float* __restrict__ Whh_b,
          const float* __restrict__ masks, float* __restrict__ out)
{
    extern __shared__ __align__(16) char smem[];
    float* wsm = (float*)smem;                 // [k][kk][4]
    float* hb0 = (float*)(smem + 131072);      // [128][8]
    float* hb1 = (float*)(smem + 135168);

    const int tid  = threadIdx.x;
    const int rank = blockIdx.x;               // k-half == cluster rank
    const int bt   = blockIdx.y;               // 0..31
    const int d    = blockIdx.z;
    const int K0   = rank * 64;
    const int bb0  = bt * 8;

    const int kk = tid >> 2;                   // 0..63: owned k-output
    const int bp = tid & 3;                    // batch-pair
    const int b0 = bb0 + 2 * bp;

    const float* Whh = d ? Whh_b : Whh_f;

    // ---- stage weights once: thread <-> one gate-row (g = tid&3, kk2 = tid>>2)
    {
        int g2  = tid & 3;
        int kk2 = tid >> 2;
        const float4* src = (const float4*)&Whh[(g2 * 128 + K0 + kk2) * 128];
        float* dst = wsm + kk2 * 4 + g2;
        #pragma unroll
        for (int q = 0; q < 32; ++q) {
            float4 v = src[q];
            dst[(4 * q + 0) * 256] = v.x;
            dst[(4 * q + 1) * 256] = v.y;
            dst[(4 * q + 2) * 256] = v.z;
            dst[(4 * q + 3) * 256] = v.w;
        }
    }
    // zero h buffer for step 0
    for (int i = tid; i < 1024; i += 256) hb0[i] = 0.f;

    // precompute peer push addresses (both parities)
    const unsigned off = (unsigned)(((K0 + kk) * 8 + 2 * bp) * 4);
    unsigned rem0, rem1;
    {
        unsigned a0 = smem_u32(hb0) + off;
        unsigned a1 = smem_u32(hb1) + off;
        unsigned pr = rank ^ 1;
        asm("mapa.shared::cluster.u32 %0, %1, %2;" : "=r"(rem0) : "r"(a0), "r"(pr));
        asm("mapa.shared::cluster.u32 %0, %1, %2;" : "=r"(rem1) : "r"(a1), "r"(pr));
    }
    float* loc0 = (float*)(smem + 131072 + off);
    float* loc1 = (float*)(smem + 135168 + off);

    // per-thread state
    float c0 = 0.f, c1 = 0.f;
    float m0 = -3.0e38f, m1 = -3.0e38f;

    const int tstep = d ? -1 : 1;
    int t = d ? (TT - 1) : 0;
    const float* xbase = &g_xgT[d][0][0][b0];

    float2 nxi, nxf, nxg, nxo;
    {
        const float* p = xbase + (size_t)t * (G4 * BB);
        nxi = *(const float2*)&p[(  0 + K0 + kk) * BB];
        nxf = *(const float2*)&p[(128 + K0 + kk) * BB];
        nxg = *(const float2*)&p[(256 + K0 + kk) * BB];
        nxo = *(const float2*)&p[(384 + K0 + kk) * BB];
    }
    float pen0 = (1.0f - __ldg(&masks[(b0)     * TT + t])) * 1e8f;
    float pen1 = (1.0f - __ldg(&masks[(b0 + 1) * TT + t])) * 1e8f;

    __syncthreads();   // weights + hb0 ready

    int cur = 0;
    for (int s = 0; s < TT; ++s) {
        // init accumulators from prefetched xg
        ull aif0 = pack2(nxi.x, nxf.x);
        ull aif1 = pack2(nxi.y, nxf.y);
        ull ago0 = pack2(nxg.x, nxo.x);
        ull ago1 = pack2(nxg.y, nxo.y);
        float npen0 = pen0, npen1 = pen1;

        // prefetch next step
        {
            int t2 = t + tstep;
            t2 = (t2 < 0) ? 0 : (t2 > TT - 1 ? TT - 1 : t2);
            const float* p = xbase + (size_t)t2 * (G4 * BB);
            nxi = *(const float2*)&p[(  0 + K0 + kk) * BB];
            nxf = *(const float2*)&p[(128 + K0 + kk) * BB];
            nxg = *(const float2*)&p[(256 + K0 + kk) * BB];
            nxo = *(const float2*)&p[(384 + K0 + kk) * BB];
            pen0 = (1.0f - __ldg(&masks[(b0)     * TT + t2])) * 1e8f;
            pen1 = (1.0f - __ldg(&masks[(b0 + 1) * TT + t2])) * 1e8f;
        }

        // ---- recurrent MAC: 4 gates x 2 batches over k=0..127 ----
        // wsm k-row = 256 floats = 64 ulonglong2  ->  stride 64 (bug was 16)
        const float* hc = cur ? hb1 : hb0;
        const ulonglong2* wp = (const ulonglong2*)(wsm + kk * 4);
        const float2*     hp = (const float2*)(hc + 2 * bp);
        #pragma unroll 8
        for (int k = 0; k < 128; ++k) {
            ulonglong2 wv = wp[k * 64];        // (wi,wf),(wg,wo) LDS.128
            float2     hv = hp[k * 4];         // h[k][b0], h[k][b0+1] LDS.64
            ull h0 = pack2(hv.x, hv.x);
            ull h1 = pack2(hv.y, hv.y);
            fma2(h0, wv.x, aif0);
            fma2(h0, wv.y, ago0);
            fma2(h1, wv.x, aif1);
            fma2(h1, wv.y, ago1);
        }

        // ---- c/h update + running masked max (all in registers) ----
        float gi, gf, gg, go, hv0, hv1;
        unpack2(aif0, gi, gf); unpack2(ago0, gg, go);
        c0 = sigf(gf) * c0 + sigf(gi) * tanhf_(gg);
        hv0 = sigf(go) * tanhf_(c0);
        m0 = fmaxf(m0, hv0 - npen0);

        unpack2(aif1, gi, gf); unpack2(ago1, gg, go);
        c1 = sigf(gf) * c1 + sigf(gi) * tanhf_(gg);
        hv1 = sigf(go) * tanhf_(c1);
        m1 = fmaxf(m1, hv1 - npen1);

        if (s < TT - 1) {
            // push h to next buffer: local + one DSMEM peer
            if (cur) { *(float2*)loc0 = make_float2(hv0, hv1); }
            else     { *(float2*)loc1 = make_float2(hv0, hv1); }
            unsigned ra = cur ? rem0 : rem1;
            asm volatile("st.shared::cluster.v2.f32 [%0], {%1,%2};"
                         :: "r"(ra), "f"(hv0), "f"(hv1) : "memory");
            // 2-CTA split barrier: release our pushes / acquire peer's
            asm volatile("barrier.cluster.arrive.aligned;" ::: "memory");
            asm volatile("barrier.cluster.wait.aligned;"   ::: "memory");
        }

        cur ^= 1;
        t += tstep;
    }

    // output: thread owns (k = K0+kk, batches b0, b0+1)
    out[(b0)     * HID + d * HH + K0 + kk] = m0;
    out[(b0 + 1) * HID + d * HH + K0 + kk] = m1;
}

// ---------------------------------------------------------------------------
extern "C" void kernel_launch(void* const* d_in, const int* in_sizes, int n_in,
                              void* d_out, int out_size)
{
    (void)in_sizes; (void)n_in; (void)out_size;
    const int*   idx   = (const int*)  d_in[0];
    const float* masks = (const float*)d_in[1];
    const float* emb   = (const float*)d_in[2];
    const float* Wih_f = (const float*)d_in[3];
    const float* Whh_f = (const float*)d_in[4];
    const float* bih_f = (const float*)d_in[5];
    const float* bhh_f = (const float*)d_in[6];
    const float* Wih_b = (const float*)d_in[7];
    const float* Whh_b = (const float*)d_in[8];
    const float* bih_b = (const float*)d_in[9];
    const float* bhh_b = (const float*)d_in[10];
    float* out = (float*)d_out;

    static int configured = 0;
    if (!configured) {
        cudaFuncSetAttribute(lstm_pair,
                             cudaFuncAttributeMaxDynamicSharedMemorySize, SMEM_BYTES);
        configured = 1;
    }

    embed_gemm<<<dim3(8, TT), 256>>>(idx, emb, Wih_f, bih_f, bhh_f,
                                     Wih_b, bih_b, bhh_b);
    lstm_pair<<<dim3(2, 32, 2), 256, SMEM_BYTES>>>(Whh_f, Whh_b, masks, out);
}